// round 1
// baseline (speedup 1.0000x reference)
#include <cuda_runtime.h>
#include <cuda_bf16.h>
#include <math.h>

#define SEQ   4096
#define DIM   512
#define KCONV 3
#define KTOT  (DIM * KCONV)      // 1536
#define MAXOUT (4 * SEQ)         // 16384
#define LN_EPS 1e-5f

// -------- scratch (no allocations allowed) --------
__device__ float g_Bt1[KTOT * DIM];   // conv1 weights as [K=1536][N=512]
__device__ float g_Bt2[KTOT * DIM];   // conv2 weights as [K=1536][N=512]
__device__ float g_y1[SEQ * DIM];     // conv1 output (pre-LN)
__device__ float g_x1[SEQ * DIM];     // LN1+ReLU output
__device__ float g_y2[SEQ * DIM];     // conv2 output (pre-LN)
__device__ int   g_dur[SEQ];
__device__ int   g_cum[SEQ];

// ============================================================
// Weight permute: w[o][d][k] -> Bt[k*512+d][o]
// ============================================================
__global__ void wtrans_kernel(const float* __restrict__ w1,
                              const float* __restrict__ w2) {
    int idx = blockIdx.x * 256 + threadIdx.x;       // 0 .. 786431
    const float* w = blockIdx.y ? w2 : w1;
    float* Bt      = blockIdx.y ? g_Bt2 : g_Bt1;
    int o = idx & 511;
    int c = idx >> 9;          // 0..1535
    int k = c >> 9;            // 0..2
    int d = c & 511;
    Bt[idx] = w[o * KTOT + d * KCONV + k];
}

// ============================================================
// Conv-as-GEMM: dst[s][o] = sum_c A[s][c] * Bt[c][o] + bias[o]
// A[s][k*512+d] = src[s+k-1][d] (zero padded), implicit.
// BM=128, BN=64, BK=16, 256 threads, 8x4 per thread.
// ============================================================
template <int PASS>
__global__ __launch_bounds__(256, 2)
void conv_gemm_kernel(const float* __restrict__ enc,
                      const float* __restrict__ bias) {
    const float* src = (PASS == 0) ? enc : g_x1;
    const float* Bt  = (PASS == 0) ? g_Bt1 : g_Bt2;
    float* dst       = (PASS == 0) ? g_y1 : g_y2;

    __shared__ float As[16][132];   // [BK][BM+pad]
    __shared__ float Bs[16][64];    // [BK][BN]

    const int bm = blockIdx.x * 128;
    const int bn = blockIdx.y * 64;
    const int tid = threadIdx.x;
    const int tx = tid & 15;        // 0..15 -> cols
    const int ty = tid >> 4;        // 0..15 -> rows

    float acc[8][4];
#pragma unroll
    for (int i = 0; i < 8; i++)
#pragma unroll
        for (int j = 0; j < 4; j++) acc[i][j] = 0.f;

    for (int k0 = 0; k0 < KTOT; k0 += 16) {
        const int kseg  = k0 >> 9;       // constant across the BK tile
        const int dbase = k0 & 511;
        // load A tile (implicit shifted rows of src)
#pragma unroll
        for (int i = 0; i < 8; i++) {
            int e  = tid + i * 256;      // 0..2047
            int kk = e & 15;
            int r  = e >> 4;             // 0..127
            int srow = bm + r + kseg - 1;
            float v = 0.f;
            if (srow >= 0 && srow < SEQ) v = src[srow * DIM + dbase + kk];
            As[kk][r] = v;
        }
        // load B tile
#pragma unroll
        for (int i = 0; i < 4; i++) {
            int e  = tid + i * 256;      // 0..1023
            int kk = e >> 6;
            int n  = e & 63;
            Bs[kk][n] = Bt[(k0 + kk) * DIM + bn + n];
        }
        __syncthreads();

#pragma unroll
        for (int kk = 0; kk < 16; kk++) {
            float4 a0 = *(const float4*)&As[kk][ty * 8];
            float4 a1 = *(const float4*)&As[kk][ty * 8 + 4];
            float4 b0 = *(const float4*)&Bs[kk][tx * 4];
            float a[8] = {a0.x, a0.y, a0.z, a0.w, a1.x, a1.y, a1.z, a1.w};
            float b[4] = {b0.x, b0.y, b0.z, b0.w};
#pragma unroll
            for (int i = 0; i < 8; i++)
#pragma unroll
                for (int j = 0; j < 4; j++)
                    acc[i][j] = fmaf(a[i], b[j], acc[i][j]);
        }
        __syncthreads();
    }

    float4 bb = *(const float4*)&bias[bn + tx * 4];
#pragma unroll
    for (int i = 0; i < 8; i++) {
        int row = bm + ty * 8 + i;
        float4 o;
        o.x = acc[i][0] + bb.x;
        o.y = acc[i][1] + bb.y;
        o.z = acc[i][2] + bb.z;
        o.w = acc[i][3] + bb.w;
        *(float4*)&dst[row * DIM + bn + tx * 4] = o;
    }
}

// ------------- block reduction helper (128 threads) -------------
__device__ __forceinline__ void reduce2_128(float& s, float& q, float* sh) {
#pragma unroll
    for (int off = 16; off; off >>= 1) {
        s += __shfl_down_sync(0xFFFFFFFFu, s, off);
        q += __shfl_down_sync(0xFFFFFFFFu, q, off);
    }
    int w = threadIdx.x >> 5;
    if ((threadIdx.x & 31) == 0) { sh[w] = s; sh[4 + w] = q; }
    __syncthreads();
    s = sh[0] + sh[1] + sh[2] + sh[3];
    q = sh[4] + sh[5] + sh[6] + sh[7];
}

// ============================================================
// LN1 + ReLU: g_y1 -> g_x1.  128 threads/row, float4.
// ============================================================
__global__ __launch_bounds__(128)
void ln_relu_kernel(const float* __restrict__ g,
                    const float* __restrict__ b) {
    __shared__ float sh[8];
    int row = blockIdx.x;
    int tid = threadIdx.x;
    float4 v = ((const float4*)(g_y1 + row * DIM))[tid];
    float s = v.x + v.y + v.z + v.w;
    float q = v.x * v.x + v.y * v.y + v.z * v.z + v.w * v.w;
    reduce2_128(s, q, sh);
    float mean = s * (1.f / DIM);
    float var  = q * (1.f / DIM) - mean * mean;
    float rstd = rsqrtf(var + LN_EPS);
    float4 gg = ((const float4*)g)[tid];
    float4 bb = ((const float4*)b)[tid];
    float4 o;
    o.x = fmaxf((v.x - mean) * rstd * gg.x + bb.x, 0.f);
    o.y = fmaxf((v.y - mean) * rstd * gg.y + bb.y, 0.f);
    o.z = fmaxf((v.z - mean) * rstd * gg.z + bb.z, 0.f);
    o.w = fmaxf((v.w - mean) * rstd * gg.w + bb.w, 0.f);
    ((float4*)(g_x1 + row * DIM))[tid] = o;
}

// ============================================================
// LN2 + ReLU + linear + duration: g_y2 -> g_dur (x2 never stored)
// ============================================================
__global__ __launch_bounds__(128)
void ln_dur_kernel(const float* __restrict__ g,
                   const float* __restrict__ b,
                   const float* __restrict__ lw,
                   const float* __restrict__ lb) {
    __shared__ float sh[8];
    int row = blockIdx.x;
    int tid = threadIdx.x;
    float4 v = ((const float4*)(g_y2 + row * DIM))[tid];
    float s = v.x + v.y + v.z + v.w;
    float q = v.x * v.x + v.y * v.y + v.z * v.z + v.w * v.w;
    reduce2_128(s, q, sh);
    float mean = s * (1.f / DIM);
    float var  = q * (1.f / DIM) - mean * mean;
    float rstd = rsqrtf(var + LN_EPS);
    float4 gg = ((const float4*)g)[tid];
    float4 bb = ((const float4*)b)[tid];
    float4 ww = ((const float4*)lw)[tid];
    float ox = fmaxf((v.x - mean) * rstd * gg.x + bb.x, 0.f);
    float oy = fmaxf((v.y - mean) * rstd * gg.y + bb.y, 0.f);
    float oz = fmaxf((v.z - mean) * rstd * gg.z + bb.z, 0.f);
    float ow = fmaxf((v.w - mean) * rstd * gg.w + bb.w, 0.f);
    float t = ox * ww.x + oy * ww.y + oz * ww.z + ow * ww.w;
    __syncthreads();   // protect sh reuse
    float dummy = 0.f;
    reduce2_128(t, dummy, sh);
    if (tid == 0) {
        float pred = fmaxf(t + lb[0], 0.f);
        g_dur[row] = (int)floorf(pred + 0.5f);
    }
}

// ============================================================
// Inclusive cumsum of g_dur (4096 ints), single block.
// ============================================================
__global__ __launch_bounds__(1024)
void cumsum_kernel() {
    __shared__ int part[1024];
    int tid = threadIdx.x;
    int v[4];
    int s = 0;
#pragma unroll
    for (int i = 0; i < 4; i++) { v[i] = g_dur[tid * 4 + i]; s += v[i]; }
    part[tid] = s;
    __syncthreads();
    for (int off = 1; off < 1024; off <<= 1) {
        int t = 0;
        if (tid >= off) t = part[tid - off];
        __syncthreads();
        if (tid >= off) part[tid] += t;
        __syncthreads();
    }
    int run = (tid > 0) ? part[tid - 1] : 0;
#pragma unroll
    for (int i = 0; i < 4; i++) { run += v[i]; g_cum[tid * 4 + i] = run; }
}

// ============================================================
// Length regulation: one block per output frame t.
// searchsorted(cum, t, 'right'), gather 512 floats, pos arange.
// ============================================================
__global__ __launch_bounds__(128)
void gather_kernel(const float* __restrict__ enc,
                   float* __restrict__ out,
                   float* __restrict__ pos,
                   int write_pos) {
    int t = blockIdx.x;
    int tid = threadIdx.x;
    int total = g_cum[SEQ - 1];
    float4 val = make_float4(0.f, 0.f, 0.f, 0.f);
    if (t < total) {
        int lo = 0, hi = SEQ;
        while (lo < hi) {
            int mid = (lo + hi) >> 1;
            if (g_cum[mid] <= t) lo = mid + 1; else hi = mid;
        }
        if (lo > SEQ - 1) lo = SEQ - 1;
        val = ((const float4*)(enc + lo * DIM))[tid];
    }
    ((float4*)(out + t * DIM))[tid] = val;
    if (write_pos && tid == 0) pos[t] = (float)(t + 1);
}

// ============================================================
extern "C" void kernel_launch(void* const* d_in, const int* in_sizes, int n_in,
                              void* d_out, int out_size) {
    const float* enc = (const float*)d_in[0];
    const float* c1w = (const float*)d_in[1];
    const float* c1b = (const float*)d_in[2];
    const float* g1  = (const float*)d_in[3];
    const float* b1  = (const float*)d_in[4];
    const float* c2w = (const float*)d_in[5];
    const float* c2b = (const float*)d_in[6];
    const float* g2  = (const float*)d_in[7];
    const float* b2  = (const float*)d_in[8];
    const float* lw  = (const float*)d_in[9];
    const float* lb  = (const float*)d_in[10];
    float* out = (float*)d_out;

    wtrans_kernel<<<dim3((KTOT * DIM) / 256, 2), 256>>>(c1w, c2w);
    conv_gemm_kernel<0><<<dim3(SEQ / 128, DIM / 64), 256>>>(enc, c1b);
    ln_relu_kernel<<<SEQ, 128>>>(g1, b1);
    conv_gemm_kernel<1><<<dim3(SEQ / 128, DIM / 64), 256>>>(enc, c2b);
    ln_dur_kernel<<<SEQ, 128>>>(g2, b2, lw, lb);
    cumsum_kernel<<<1, 1024>>>();

    int write_pos = (out_size >= MAXOUT * DIM + MAXOUT) ? 1 : 0;
    gather_kernel<<<MAXOUT, 128>>>(enc, out, out + (size_t)MAXOUT * DIM, write_pos);
}

// round 2
// speedup vs baseline: 1.0025x; 1.0025x over previous
#include <cuda_runtime.h>
#include <cuda_bf16.h>
#include <math.h>

#define SEQ   4096
#define DIM   512
#define KCONV 3
#define KTOT  (DIM * KCONV)      // 1536
#define MAXOUT (4 * SEQ)         // 16384
#define LN_EPS 1e-5f

// -------- scratch (no allocations allowed) --------
__device__ float g_Bt1[KTOT * DIM];   // conv1 weights as [K=1536][N=512]
__device__ float g_Bt2[KTOT * DIM];   // conv2 weights as [K=1536][N=512]
__device__ float g_y1[SEQ * DIM];     // conv1 output (pre-LN)
__device__ float g_x1[SEQ * DIM];     // LN1+ReLU output
__device__ float g_y2[SEQ * DIM];     // conv2 output (pre-LN)
__device__ int   g_dur[SEQ];
__device__ int   g_cum[SEQ];

// ============================================================
// Weight permute: w[o][d][k] -> Bt[k*512+d][o]
// ============================================================
__global__ void wtrans_kernel(const float* __restrict__ w1,
                              const float* __restrict__ w2) {
    int idx = blockIdx.x * 256 + threadIdx.x;       // 0 .. 786431
    const float* w = blockIdx.y ? w2 : w1;
    float* Bt      = blockIdx.y ? g_Bt2 : g_Bt1;
    int o = idx & 511;
    int c = idx >> 9;          // 0..1535
    int k = c >> 9;            // 0..2
    int d = c & 511;
    Bt[idx] = w[o * KTOT + d * KCONV + k];
}

// ============================================================
// Conv-as-GEMM: dst[s][o] = sum_c A[s][c] * Bt[c][o] + bias[o]
// A[s][k*512+d] = src[s+k-1][d] (zero padded), implicit im2col.
// BM=128, BN=128, BK=16, 256 threads, 8x8 microtile,
// smem double buffering + register prefetch.
// ============================================================
template <int PASS>
__global__ __launch_bounds__(256)
void conv_gemm_kernel(const float* __restrict__ enc,
                      const float* __restrict__ bias) {
    const float* src = (PASS == 0) ? enc : g_x1;
    const float* Bt  = (PASS == 0) ? g_Bt1 : g_Bt2;
    float* dst       = (PASS == 0) ? g_y1 : g_y2;

    __shared__ float As[2][16][128];   // [buf][k][m]
    __shared__ float Bs[2][16][128];   // [buf][k][n]

    const int bm = blockIdx.x * 128;
    const int bn = blockIdx.y * 128;
    const int tid = threadIdx.x;
    const int tx = tid & 15;        // n-dim (8 cols each)
    const int ty = tid >> 4;        // m-dim (8 rows each)

    // A global load mapping: m = tid>>1, 8 consecutive k starting at (tid&1)*8
    const int am = tid >> 1;
    const int ah = (tid & 1) * 8;
    // B global load mapping: e = tid + i*256 -> kk = e>>5, n4 = (e&31)*4
    const int kk0 = tid >> 5;             // 0..7
    const int n40 = (tid & 31) * 4;       // 0..124
    const int kk1 = kk0 + 8;              // 8..15

    float acc[8][8];
#pragma unroll
    for (int i = 0; i < 8; i++)
#pragma unroll
        for (int j = 0; j < 8; j++) acc[i][j] = 0.f;

    const int NK = KTOT / 16;   // 96

    // ---- prologue: tile 0 -> smem buf 0
    {
        // A: kseg = 0, dbase = 0
        int srow = bm + am - 1;
        float4 a0 = make_float4(0.f, 0.f, 0.f, 0.f);
        float4 a1 = a0;
        if (srow >= 0 && srow < SEQ) {
            a0 = *(const float4*)&src[srow * DIM + ah];
            a1 = *(const float4*)&src[srow * DIM + ah + 4];
        }
        As[0][ah + 0][am] = a0.x; As[0][ah + 1][am] = a0.y;
        As[0][ah + 2][am] = a0.z; As[0][ah + 3][am] = a0.w;
        As[0][ah + 4][am] = a1.x; As[0][ah + 5][am] = a1.y;
        As[0][ah + 6][am] = a1.z; As[0][ah + 7][am] = a1.w;
        *(float4*)&Bs[0][kk0][n40] = *(const float4*)&Bt[kk0 * DIM + bn + n40];
        *(float4*)&Bs[0][kk1][n40] = *(const float4*)&Bt[kk1 * DIM + bn + n40];
    }
    __syncthreads();

    int buf = 0;
#pragma unroll 1
    for (int t = 0; t < NK; ++t) {
        const int tn = t + 1;
        float4 a0, a1, b0, b1;
        if (tn < NK) {
            const int k0 = tn * 16;
            const int kseg  = k0 >> 9;
            const int dbase = k0 & 511;
            int srow = bm + am + kseg - 1;
            a0 = make_float4(0.f, 0.f, 0.f, 0.f);
            a1 = a0;
            if (srow >= 0 && srow < SEQ) {
                a0 = *(const float4*)&src[srow * DIM + dbase + ah];
                a1 = *(const float4*)&src[srow * DIM + dbase + ah + 4];
            }
            b0 = *(const float4*)&Bt[(k0 + kk0) * DIM + bn + n40];
            b1 = *(const float4*)&Bt[(k0 + kk1) * DIM + bn + n40];
        }

        // ---- compute on current buffer
#pragma unroll
        for (int kk = 0; kk < 16; kk++) {
            float4 x0 = *(const float4*)&As[buf][kk][ty * 8];
            float4 x1 = *(const float4*)&As[buf][kk][ty * 8 + 4];
            float4 y0 = *(const float4*)&Bs[buf][kk][tx * 8];
            float4 y1 = *(const float4*)&Bs[buf][kk][tx * 8 + 4];
            float a[8] = {x0.x, x0.y, x0.z, x0.w, x1.x, x1.y, x1.z, x1.w};
            float b[8] = {y0.x, y0.y, y0.z, y0.w, y1.x, y1.y, y1.z, y1.w};
#pragma unroll
            for (int i = 0; i < 8; i++)
#pragma unroll
                for (int j = 0; j < 8; j++)
                    acc[i][j] = fmaf(a[i], b[j], acc[i][j]);
        }

        if (tn < NK) {
            const int nb = buf ^ 1;
            As[nb][ah + 0][am] = a0.x; As[nb][ah + 1][am] = a0.y;
            As[nb][ah + 2][am] = a0.z; As[nb][ah + 3][am] = a0.w;
            As[nb][ah + 4][am] = a1.x; As[nb][ah + 5][am] = a1.y;
            As[nb][ah + 6][am] = a1.z; As[nb][ah + 7][am] = a1.w;
            *(float4*)&Bs[nb][kk0][n40] = b0;
            *(float4*)&Bs[nb][kk1][n40] = b1;
            __syncthreads();
            buf = nb;
        }
    }

    // ---- epilogue
    float4 bb0 = *(const float4*)&bias[bn + tx * 8];
    float4 bb1 = *(const float4*)&bias[bn + tx * 8 + 4];
#pragma unroll
    for (int i = 0; i < 8; i++) {
        int row = bm + ty * 8 + i;
        float4 o0, o1;
        o0.x = acc[i][0] + bb0.x; o0.y = acc[i][1] + bb0.y;
        o0.z = acc[i][2] + bb0.z; o0.w = acc[i][3] + bb0.w;
        o1.x = acc[i][4] + bb1.x; o1.y = acc[i][5] + bb1.y;
        o1.z = acc[i][6] + bb1.z; o1.w = acc[i][7] + bb1.w;
        *(float4*)&dst[row * DIM + bn + tx * 8]     = o0;
        *(float4*)&dst[row * DIM + bn + tx * 8 + 4] = o1;
    }
}

// ------------- block reduction helper (128 threads) -------------
__device__ __forceinline__ void reduce2_128(float& s, float& q, float* sh) {
#pragma unroll
    for (int off = 16; off; off >>= 1) {
        s += __shfl_down_sync(0xFFFFFFFFu, s, off);
        q += __shfl_down_sync(0xFFFFFFFFu, q, off);
    }
    int w = threadIdx.x >> 5;
    if ((threadIdx.x & 31) == 0) { sh[w] = s; sh[4 + w] = q; }
    __syncthreads();
    s = sh[0] + sh[1] + sh[2] + sh[3];
    q = sh[4] + sh[5] + sh[6] + sh[7];
}

// ============================================================
// LN1 + ReLU: g_y1 -> g_x1.  128 threads/row, float4.
// ============================================================
__global__ __launch_bounds__(128)
void ln_relu_kernel(const float* __restrict__ g,
                    const float* __restrict__ b) {
    __shared__ float sh[8];
    int row = blockIdx.x;
    int tid = threadIdx.x;
    float4 v = ((const float4*)(g_y1 + row * DIM))[tid];
    float s = v.x + v.y + v.z + v.w;
    float q = v.x * v.x + v.y * v.y + v.z * v.z + v.w * v.w;
    reduce2_128(s, q, sh);
    float mean = s * (1.f / DIM);
    float var  = q * (1.f / DIM) - mean * mean;
    float rstd = rsqrtf(var + LN_EPS);
    float4 gg = ((const float4*)g)[tid];
    float4 bb = ((const float4*)b)[tid];
    float4 o;
    o.x = fmaxf((v.x - mean) * rstd * gg.x + bb.x, 0.f);
    o.y = fmaxf((v.y - mean) * rstd * gg.y + bb.y, 0.f);
    o.z = fmaxf((v.z - mean) * rstd * gg.z + bb.z, 0.f);
    o.w = fmaxf((v.w - mean) * rstd * gg.w + bb.w, 0.f);
    ((float4*)(g_x1 + row * DIM))[tid] = o;
}

// ============================================================
// LN2 + ReLU + linear + duration: g_y2 -> g_dur (x2 never stored)
// ============================================================
__global__ __launch_bounds__(128)
void ln_dur_kernel(const float* __restrict__ g,
                   const float* __restrict__ b,
                   const float* __restrict__ lw,
                   const float* __restrict__ lb) {
    __shared__ float sh[8];
    int row = blockIdx.x;
    int tid = threadIdx.x;
    float4 v = ((const float4*)(g_y2 + row * DIM))[tid];
    float s = v.x + v.y + v.z + v.w;
    float q = v.x * v.x + v.y * v.y + v.z * v.z + v.w * v.w;
    reduce2_128(s, q, sh);
    float mean = s * (1.f / DIM);
    float var  = q * (1.f / DIM) - mean * mean;
    float rstd = rsqrtf(var + LN_EPS);
    float4 gg = ((const float4*)g)[tid];
    float4 bb = ((const float4*)b)[tid];
    float4 ww = ((const float4*)lw)[tid];
    float ox = fmaxf((v.x - mean) * rstd * gg.x + bb.x, 0.f);
    float oy = fmaxf((v.y - mean) * rstd * gg.y + bb.y, 0.f);
    float oz = fmaxf((v.z - mean) * rstd * gg.z + bb.z, 0.f);
    float ow = fmaxf((v.w - mean) * rstd * gg.w + bb.w, 0.f);
    float t = ox * ww.x + oy * ww.y + oz * ww.z + ow * ww.w;
    __syncthreads();   // protect sh reuse
    float dummy = 0.f;
    reduce2_128(t, dummy, sh);
    if (tid == 0) {
        float pred = fmaxf(t + lb[0], 0.f);
        g_dur[row] = (int)floorf(pred + 0.5f);
    }
}

// ============================================================
// Inclusive cumsum of g_dur (4096 ints), single block.
// ============================================================
__global__ __launch_bounds__(1024)
void cumsum_kernel() {
    __shared__ int part[1024];
    int tid = threadIdx.x;
    int v[4];
    int s = 0;
#pragma unroll
    for (int i = 0; i < 4; i++) { v[i] = g_dur[tid * 4 + i]; s += v[i]; }
    part[tid] = s;
    __syncthreads();
    for (int off = 1; off < 1024; off <<= 1) {
        int t = 0;
        if (tid >= off) t = part[tid - off];
        __syncthreads();
        if (tid >= off) part[tid] += t;
        __syncthreads();
    }
    int run = (tid > 0) ? part[tid - 1] : 0;
#pragma unroll
    for (int i = 0; i < 4; i++) { run += v[i]; g_cum[tid * 4 + i] = run; }
}

// ============================================================
// Length regulation: one block per output frame t.
// ============================================================
__global__ __launch_bounds__(128)
void gather_kernel(const float* __restrict__ enc,
                   float* __restrict__ out,
                   float* __restrict__ pos,
                   int write_pos) {
    int t = blockIdx.x;
    int tid = threadIdx.x;
    int total = g_cum[SEQ - 1];
    float4 val = make_float4(0.f, 0.f, 0.f, 0.f);
    if (t < total) {
        int lo = 0, hi = SEQ;
        while (lo < hi) {
            int mid = (lo + hi) >> 1;
            if (g_cum[mid] <= t) lo = mid + 1; else hi = mid;
        }
        if (lo > SEQ - 1) lo = SEQ - 1;
        val = ((const float4*)(enc + lo * DIM))[tid];
    }
    ((float4*)(out + t * DIM))[tid] = val;
    if (write_pos && tid == 0) pos[t] = (float)(t + 1);
}

// ============================================================
extern "C" void kernel_launch(void* const* d_in, const int* in_sizes, int n_in,
                              void* d_out, int out_size) {
    const float* enc = (const float*)d_in[0];
    const float* c1w = (const float*)d_in[1];
    const float* c1b = (const float*)d_in[2];
    const float* g1  = (const float*)d_in[3];
    const float* b1  = (const float*)d_in[4];
    const float* c2w = (const float*)d_in[5];
    const float* c2b = (const float*)d_in[6];
    const float* g2  = (const float*)d_in[7];
    const float* b2  = (const float*)d_in[8];
    const float* lw  = (const float*)d_in[9];
    const float* lb  = (const float*)d_in[10];
    float* out = (float*)d_out;

    wtrans_kernel<<<dim3((KTOT * DIM) / 256, 2), 256>>>(c1w, c2w);
    conv_gemm_kernel<0><<<dim3(SEQ / 128, DIM / 128), 256>>>(enc, c1b);
    ln_relu_kernel<<<SEQ, 128>>>(g1, b1);
    conv_gemm_kernel<1><<<dim3(SEQ / 128, DIM / 128), 256>>>(enc, c2b);
    ln_dur_kernel<<<SEQ, 128>>>(g2, b2, lw, lb);
    cumsum_kernel<<<1, 1024>>>();

    int write_pos = (out_size >= MAXOUT * DIM + MAXOUT) ? 1 : 0;
    gather_kernel<<<MAXOUT, 128>>>(enc, out, out + (size_t)MAXOUT * DIM, write_pos);
}